// round 1
// baseline (speedup 1.0000x reference)
#include <cuda_runtime.h>
#include <math.h>

#define B_ 2
#define S_ 2048
#define E_ 1024
#define H_ 16
#define D_ 64
#define M_ (B_*S_)    // 4096 rows
#define BH_ (B_*H_)   // 32 head-batches

// Scratch (device globals: no allocation allowed)
__device__ float g_q[(size_t)BH_*S_*D_];
__device__ float g_k[(size_t)BH_*S_*D_];
__device__ float g_v[(size_t)BH_*S_*D_];
__device__ float g_o[(size_t)M_*E_];

// ---------------------------------------------------------------------------
// QKV projection: theta[m,n] = sum_k x[m,k] * W[n,k]
// Written directly into [B,H,S,D] layout for the attention kernel.
// 128x128x16 tile, 256 threads, 8x8 per-thread (4+4 split fragments).
// ---------------------------------------------------------------------------
__global__ __launch_bounds__(256) void qkv_gemm_kernel(
    const float* __restrict__ x,
    const float* __restrict__ Wq,
    const float* __restrict__ Wk,
    const float* __restrict__ Wv)
{
    const float* W   = (blockIdx.z == 0) ? Wq : (blockIdx.z == 1) ? Wk : Wv;
    float*       out = (blockIdx.z == 0) ? g_q : (blockIdx.z == 1) ? g_k : g_v;

    __shared__ float As[16][128];
    __shared__ float Bs[16][128];

    const int tid = threadIdx.x;
    const int tx  = tid & 15, ty = tid >> 4;
    const int m0  = blockIdx.y * 128;
    const int n0  = blockIdx.x * 128;

    float c[8][8];
#pragma unroll
    for (int i = 0; i < 8; i++)
#pragma unroll
        for (int j = 0; j < 8; j++) c[i][j] = 0.f;

    const int lr = tid >> 2;   // 0..63
    const int lc = tid & 3;    // float4 chunk in K-slab

    for (int k0 = 0; k0 < E_; k0 += 16) {
#pragma unroll
        for (int h = 0; h < 2; h++) {
            int r = lr + 64 * h;
            float4 va = *(const float4*)(x + (size_t)(m0 + r) * E_ + k0 + lc * 4);
            As[lc*4+0][r] = va.x; As[lc*4+1][r] = va.y;
            As[lc*4+2][r] = va.z; As[lc*4+3][r] = va.w;
            float4 vb = *(const float4*)(W + (size_t)(n0 + r) * E_ + k0 + lc * 4);
            Bs[lc*4+0][r] = vb.x; Bs[lc*4+1][r] = vb.y;
            Bs[lc*4+2][r] = vb.z; Bs[lc*4+3][r] = vb.w;
        }
        __syncthreads();
#pragma unroll
        for (int k = 0; k < 16; k++) {
            float4 a0 = *(float4*)&As[k][ty*4];
            float4 a1 = *(float4*)&As[k][64 + ty*4];
            float4 b0 = *(float4*)&Bs[k][tx*4];
            float4 b1 = *(float4*)&Bs[k][64 + tx*4];
            float a[8] = {a0.x,a0.y,a0.z,a0.w,a1.x,a1.y,a1.z,a1.w};
            float b[8] = {b0.x,b0.y,b0.z,b0.w,b1.x,b1.y,b1.z,b1.w};
#pragma unroll
            for (int i = 0; i < 8; i++)
#pragma unroll
                for (int j = 0; j < 8; j++)
                    c[i][j] += a[i] * b[j];
        }
        __syncthreads();
    }

    // Scatter epilogue into [B,H,S,D] (4-wide column fragments never cross a head)
#pragma unroll
    for (int ih = 0; ih < 2; ih++) {
#pragma unroll
        for (int i = 0; i < 4; i++) {
            int m = m0 + ih * 64 + ty * 4 + i;
            int b = m >> 11, s = m & (S_ - 1);
#pragma unroll
            for (int jh = 0; jh < 2; jh++) {
                int n  = n0 + jh * 64 + tx * 4;
                int hh = n >> 6, d = n & 63;
                float4 v;
                v.x = c[ih*4+i][jh*4+0]; v.y = c[ih*4+i][jh*4+1];
                v.z = c[ih*4+i][jh*4+2]; v.w = c[ih*4+i][jh*4+3];
                *(float4*)(out + (((size_t)(b * H_ + hh) * S_ + s) * D_ + d)) = v;
            }
        }
    }
}

// ---------------------------------------------------------------------------
// Quantum circuit closed form: row of 64 -> cumprod(cos(theta)).
// One warp per row; float2 per lane; shfl product-scan.
// which = gw / 65536 selects q/k/v.
// ---------------------------------------------------------------------------
__global__ __launch_bounds__(256) void quantum_kernel()
{
    const int gw   = (int)((blockIdx.x * (size_t)blockDim.x + threadIdx.x) >> 5);
    const int lane = threadIdx.x & 31;
    const int nrows = BH_ * S_;          // 65536 per tensor
    const int which = gw / nrows;
    const int rr    = gw - which * nrows;
    if (which >= 3) return;
    float* buf = (which == 0) ? g_q : (which == 1) ? g_k : g_v;
    float2* row = (float2*)(buf + (size_t)rr * 64);

    float2 t = row[lane];
    float cx = cosf(t.x), cy = cosf(t.y);
    float p = cx * cy;
    float incl = p;
#pragma unroll
    for (int off = 1; off < 32; off <<= 1) {
        float nv = __shfl_up_sync(0xffffffffu, incl, off);
        if (lane >= off) incl *= nv;
    }
    float excl = __shfl_up_sync(0xffffffffu, incl, 1);
    if (lane == 0) excl = 1.f;
    float2 o;
    o.x = excl * cx;   // cumprod through even index
    o.y = excl * p;    // cumprod through odd index
    row[lane] = o;
}

// ---------------------------------------------------------------------------
// Flash attention fp32. Grid (S/64, B*H), 256 threads.
// 64x64 Q-tile per block; stream K/V in 64-row tiles; online softmax.
// Smem = exactly 48KB: Qt (transposed, pre-scaled), KP (Kt then P), Vs.
// Thread (ty,tx): rows ty*4..+3, cols/keys tx*4..+3.
// ---------------------------------------------------------------------------
__global__ __launch_bounds__(256) void flash_kernel()
{
    __shared__ float Qt[64][64];  // [d][row], pre-scaled by 1/sqrt(D)
    __shared__ float KP[64][64];  // phase 1: Kt [d][key]; phase 2: P [row][key]
    __shared__ float Vs[64][64];  // [key][d]

    const int bh = blockIdx.y;
    const int q0 = blockIdx.x * 64;
    const float* Q = g_q + (size_t)bh * S_ * D_;
    const float* K = g_k + (size_t)bh * S_ * D_;
    const float* V = g_v + (size_t)bh * S_ * D_;

    const int tid = threadIdx.x;
    const int tx = tid & 15, ty = tid >> 4;

    // Load Q tile transposed + scale
#pragma unroll
    for (int it = 0; it < 4; it++) {
        int idx = tid + 256 * it;
        int r = idx >> 4;      // 0..63
        int c4 = idx & 15;     // float4 chunk
        float4 v = *(const float4*)(Q + (size_t)(q0 + r) * 64 + c4 * 4);
        Qt[c4*4+0][r] = v.x * 0.125f;
        Qt[c4*4+1][r] = v.y * 0.125f;
        Qt[c4*4+2][r] = v.z * 0.125f;
        Qt[c4*4+3][r] = v.w * 0.125f;
    }

    float o[4][4], m[4], l[4];
#pragma unroll
    for (int i = 0; i < 4; i++) {
        m[i] = -1e30f; l[i] = 0.f;
#pragma unroll
        for (int j = 0; j < 4; j++) o[i][j] = 0.f;
    }

    for (int kv0 = 0; kv0 < S_; kv0 += 64) {
        __syncthreads();   // protects KP/Vs from previous iteration & Qt on first
#pragma unroll
        for (int it = 0; it < 4; it++) {
            int idx = tid + 256 * it;
            int r = idx >> 4;
            int c4 = idx & 15;
            float4 kv = *(const float4*)(K + (size_t)(kv0 + r) * 64 + c4 * 4);
            KP[c4*4+0][r] = kv.x; KP[c4*4+1][r] = kv.y;
            KP[c4*4+2][r] = kv.z; KP[c4*4+3][r] = kv.w;
            float4 vv = *(const float4*)(V + (size_t)(kv0 + r) * 64 + c4 * 4);
            *(float4*)&Vs[r][c4*4] = vv;
        }
        __syncthreads();

        // S = Q K^T (scaled)
        float s[4][4];
#pragma unroll
        for (int i = 0; i < 4; i++)
#pragma unroll
            for (int j = 0; j < 4; j++) s[i][j] = 0.f;
#pragma unroll 8
        for (int d = 0; d < 64; d++) {
            float4 a = *(float4*)&Qt[d][ty*4];
            float4 b = *(float4*)&KP[d][tx*4];
            float av[4] = {a.x,a.y,a.z,a.w};
            float bv[4] = {b.x,b.y,b.z,b.w};
#pragma unroll
            for (int i = 0; i < 4; i++)
#pragma unroll
                for (int j = 0; j < 4; j++)
                    s[i][j] += av[i] * bv[j];
        }
        __syncthreads();   // all done reading Kt -> safe to overwrite with P

        // Online softmax per row (rows shared by the 16 lanes with equal ty;
        // those lanes are a half-warp: xor 1,2,4,8 stays inside it)
        float p[4][4];
#pragma unroll
        for (int i = 0; i < 4; i++) {
            float rm = s[i][0];
#pragma unroll
            for (int j = 1; j < 4; j++) rm = fmaxf(rm, s[i][j]);
#pragma unroll
            for (int off = 1; off < 16; off <<= 1)
                rm = fmaxf(rm, __shfl_xor_sync(0xffffffffu, rm, off));
            float mn = fmaxf(m[i], rm);
            float sc = __expf(m[i] - mn);
            float rs = 0.f;
#pragma unroll
            for (int j = 0; j < 4; j++) { p[i][j] = __expf(s[i][j] - mn); rs += p[i][j]; }
#pragma unroll
            for (int off = 1; off < 16; off <<= 1)
                rs += __shfl_xor_sync(0xffffffffu, rs, off);
            l[i] = l[i] * sc + rs;
            m[i] = mn;
#pragma unroll
            for (int j = 0; j < 4; j++) o[i][j] *= sc;
        }
        // stash P
#pragma unroll
        for (int i = 0; i < 4; i++) {
            float4 pv = make_float4(p[i][0], p[i][1], p[i][2], p[i][3]);
            *(float4*)&KP[ty*4+i][tx*4] = pv;
        }
        __syncthreads();

        // O += P V
#pragma unroll 4
        for (int key = 0; key < 64; key++) {
            float4 b = *(float4*)&Vs[key][tx*4];
            float bv[4] = {b.x,b.y,b.z,b.w};
#pragma unroll
            for (int i = 0; i < 4; i++) {
                float av = KP[ty*4+i][key];
#pragma unroll
                for (int j = 0; j < 4; j++)
                    o[i][j] += av * bv[j];
            }
        }
    }

    // Epilogue: normalize and write [B,S,H,D] (== [B,S,E] rows for final GEMM)
    const int b = bh >> 4, h = bh & 15;
#pragma unroll
    for (int i = 0; i < 4; i++) {
        int sI = q0 + ty * 4 + i;
        float inv = 1.f / l[i];
        float4 v = make_float4(o[i][0]*inv, o[i][1]*inv, o[i][2]*inv, o[i][3]*inv);
        *(float4*)(g_o + (((size_t)(b * S_ + sI) * H_ + h) * D_ + tx * 4)) = v;
    }
}

// ---------------------------------------------------------------------------
// Output projection: out[m,n] = sum_k g_o[m,k]*Wc[n,k] + bc[n]
// ---------------------------------------------------------------------------
__global__ __launch_bounds__(256) void out_gemm_kernel(
    const float* __restrict__ Wc,
    const float* __restrict__ bc,
    float* __restrict__ out)
{
    __shared__ float As[16][128];
    __shared__ float Bs[16][128];

    const int tid = threadIdx.x;
    const int tx  = tid & 15, ty = tid >> 4;
    const int m0  = blockIdx.y * 128;
    const int n0  = blockIdx.x * 128;

    float c[8][8];
#pragma unroll
    for (int i = 0; i < 8; i++)
#pragma unroll
        for (int j = 0; j < 8; j++) c[i][j] = 0.f;

    const int lr = tid >> 2;
    const int lc = tid & 3;

    for (int k0 = 0; k0 < E_; k0 += 16) {
#pragma unroll
        for (int h = 0; h < 2; h++) {
            int r = lr + 64 * h;
            float4 va = *(const float4*)(g_o + (size_t)(m0 + r) * E_ + k0 + lc * 4);
            As[lc*4+0][r] = va.x; As[lc*4+1][r] = va.y;
            As[lc*4+2][r] = va.z; As[lc*4+3][r] = va.w;
            float4 vb = *(const float4*)(Wc + (size_t)(n0 + r) * E_ + k0 + lc * 4);
            Bs[lc*4+0][r] = vb.x; Bs[lc*4+1][r] = vb.y;
            Bs[lc*4+2][r] = vb.z; Bs[lc*4+3][r] = vb.w;
        }
        __syncthreads();
#pragma unroll
        for (int k = 0; k < 16; k++) {
            float4 a0 = *(float4*)&As[k][ty*4];
            float4 a1 = *(float4*)&As[k][64 + ty*4];
            float4 b0 = *(float4*)&Bs[k][tx*4];
            float4 b1 = *(float4*)&Bs[k][64 + tx*4];
            float a[8] = {a0.x,a0.y,a0.z,a0.w,a1.x,a1.y,a1.z,a1.w};
            float b[8] = {b0.x,b0.y,b0.z,b0.w,b1.x,b1.y,b1.z,b1.w};
#pragma unroll
            for (int i = 0; i < 8; i++)
#pragma unroll
                for (int j = 0; j < 8; j++)
                    c[i][j] += a[i] * b[j];
        }
        __syncthreads();
    }

#pragma unroll
    for (int ih = 0; ih < 2; ih++) {
#pragma unroll
        for (int i = 0; i < 4; i++) {
            int m = m0 + ih * 64 + ty * 4 + i;
#pragma unroll
            for (int jh = 0; jh < 2; jh++) {
                int n = n0 + jh * 64 + tx * 4;
                float4 bb = *(const float4*)(bc + n);
                float4 v;
                v.x = c[ih*4+i][jh*4+0] + bb.x;
                v.y = c[ih*4+i][jh*4+1] + bb.y;
                v.z = c[ih*4+i][jh*4+2] + bb.z;
                v.w = c[ih*4+i][jh*4+3] + bb.w;
                *(float4*)(out + (size_t)m * E_ + n) = v;
            }
        }
    }
}

// ---------------------------------------------------------------------------
extern "C" void kernel_launch(void* const* d_in, const int* in_sizes, int n_in,
                              void* d_out, int out_size)
{
    const float* x  = (const float*)d_in[0];
    const float* Wq = (const float*)d_in[1];
    const float* Wk = (const float*)d_in[2];
    const float* Wv = (const float*)d_in[3];
    const float* Wc = (const float*)d_in[4];
    const float* bc = (const float*)d_in[5];
    float* out = (float*)d_out;

    // 1) QKV projections -> theta in [B,H,S,D]
    dim3 g1(E_ / 128, M_ / 128, 3);
    qkv_gemm_kernel<<<g1, 256>>>(x, Wq, Wk, Wv);

    // 2) quantum circuit: cumprod(cos) over D, all three tensors in one launch
    {
        long long nwarps = 3LL * BH_ * S_;            // 196608 rows
        long long nthreads = nwarps * 32;
        int blocks = (int)((nthreads + 255) / 256);   // 24576
        quantum_kernel<<<blocks, 256>>>();
    }

    // 3) flash attention -> g_o in [B,S,E]
    dim3 g3(S_ / 64, BH_);
    flash_kernel<<<g3, 256>>>();

    // 4) output projection + bias
    dim3 g4(E_ / 128, M_ / 128);
    out_gemm_kernel<<<g4, 256>>>(Wc, bc, out);
}

// round 3
// speedup vs baseline: 2.6271x; 2.6271x over previous
#include <cuda_runtime.h>
#include <cuda_fp16.h>
#include <stdint.h>
#include <math.h>

#define B_ 2
#define S_ 2048
#define E_ 1024
#define H_ 16
#define D_ 64
#define M_ (B_*S_)    // 4096
#define BH_ (B_*H_)   // 32

// ---------------- scratch (device globals; no allocation allowed) -------------
__device__ __half g_xh[(size_t)M_*E_];
__device__ __half g_xl[(size_t)M_*E_];
__device__ __half g_wh[(size_t)4*E_*E_];
__device__ __half g_wl[(size_t)4*E_*E_];
__device__ __half g_qh[(size_t)BH_*S_*D_];
__device__ __half g_ql[(size_t)BH_*S_*D_];
__device__ __half g_kh[(size_t)BH_*S_*D_];
__device__ __half g_kl[(size_t)BH_*S_*D_];
__device__ __half g_vth[(size_t)BH_*D_*S_];   // transposed [bh][d][s]
__device__ __half g_vtl[(size_t)BH_*D_*S_];
__device__ __half g_ohh[(size_t)M_*E_];
__device__ __half g_ohl[(size_t)M_*E_];

// ---------------- helpers ----------------------------------------------------
__device__ __forceinline__ uint32_t smem_u32(const void* p) {
    uint32_t a;
    asm("{ .reg .u64 t; cvta.to.shared.u64 t, %1; cvt.u32.u64 %0, t; }" : "=r"(a) : "l"(p));
    return a;
}
__device__ __forceinline__ void cp16(uint32_t s, const void* g) {
    asm volatile("cp.async.cg.shared.global [%0], [%1], 16;" :: "r"(s), "l"(g));
}
#define CP_COMMIT() asm volatile("cp.async.commit_group;" ::: "memory")
#define CP_WAIT1()  asm volatile("cp.async.wait_group 1;" ::: "memory")

__device__ __forceinline__ void ldsm4(uint32_t addr, uint32_t r[4]) {
    asm volatile("ldmatrix.sync.aligned.m8n8.x4.shared.b16 {%0,%1,%2,%3}, [%4];"
        : "=r"(r[0]), "=r"(r[1]), "=r"(r[2]), "=r"(r[3]) : "r"(addr));
}
__device__ __forceinline__ void mma_fp16(float* c, const uint32_t* a, uint32_t b0, uint32_t b1) {
    asm volatile(
        "mma.sync.aligned.m16n8k16.row.col.f32.f16.f16.f32 "
        "{%0,%1,%2,%3}, {%4,%5,%6,%7}, {%8,%9}, {%0,%1,%2,%3};"
        : "+f"(c[0]), "+f"(c[1]), "+f"(c[2]), "+f"(c[3])
        : "r"(a[0]), "r"(a[1]), "r"(a[2]), "r"(a[3]), "r"(b0), "r"(b1));
}
__device__ __forceinline__ uint32_t pack2(float x, float y) {
    __half2 h = __floats2half2_rn(x, y);
    return *(uint32_t*)&h;
}
__device__ __forceinline__ void split16(float v, __half& h, __half& l) {
    h = __float2half_rn(v);
    l = __float2half_rn(v - __half2float(h));
}

// ---------------- fp32 -> fp16 hi/lo conversion ------------------------------
__global__ __launch_bounds__(256) void convert_kernel(
    const float* __restrict__ x,  const float* __restrict__ Wq,
    const float* __restrict__ Wk, const float* __restrict__ Wv,
    const float* __restrict__ Wc)
{
    const int seg = blockIdx.y;
    const float* src; __half* hi; __half* lo; int n4;
    if (seg == 0) { src = x;  hi = g_xh; lo = g_xl; n4 = M_*E_/4; }
    else {
        src = (seg==1)?Wq:(seg==2)?Wk:(seg==3)?Wv:Wc;
        hi = g_wh + (size_t)(seg-1)*E_*E_;
        lo = g_wl + (size_t)(seg-1)*E_*E_;
        n4 = E_*E_/4;
    }
    int i = blockIdx.x * 256 + threadIdx.x;
    if (i >= n4) return;
    float4 v = ((const float4*)src)[i];
    __half h0,h1,h2,h3,l0,l1,l2,l3;
    split16(v.x,h0,l0); split16(v.y,h1,l1); split16(v.z,h2,l2); split16(v.w,h3,l3);
    ((__half2*)hi)[2*i]   = __halves2half2(h0, h1);
    ((__half2*)hi)[2*i+1] = __halves2half2(h2, h3);
    ((__half2*)lo)[2*i]   = __halves2half2(l0, l1);
    ((__half2*)lo)[2*i+1] = __halves2half2(l2, l3);
}

// ---------------- HMMA split-fp16 GEMM ---------------------------------------
// C[m,n] = sum_k A[m,k]*B[n,k]; 128x128 tile, 8 warps, k-chunk 32, 2 stages.
// MODE 0: A=x, B=W[z]; epilogue = quantum cumprod(cos); writes q/k ([bh][s][d],
//         q scaled 0.125) and v transposed ([bh][d][s]) as fp16 hi/lo.
// MODE 1: A=attn out (hi/lo), B=Wc; epilogue adds bias -> fp32 out.
#define GROWB 80
#define GT_BYTES (128*GROWB)      // 10240
#define GSTAGE  (4*GT_BYTES)      // 40960: Ah, Al, Bh, Bl
#define GSMEM   (2*GSTAGE)        // 81920

template<int MODE>
__global__ __launch_bounds__(256) void gemm_kernel(float* __restrict__ out,
                                                   const float* __restrict__ bc)
{
    extern __shared__ char sm[];
    const uint32_t s0 = smem_u32(sm);
    const int tid = threadIdx.x;
    const int lane = tid & 31, warp = tid >> 5;
    const int wm = warp >> 2, wn = warp & 3;
    const int m0 = blockIdx.y * 128, n0 = blockIdx.x * 128;

    const __half *Ah, *Al, *Bh2, *Bl2;
    if (MODE == 0) {
        Ah = g_xh; Al = g_xl;
        Bh2 = g_wh + (size_t)blockIdx.z * E_ * E_;
        Bl2 = g_wl + (size_t)blockIdx.z * E_ * E_;
    } else {
        Ah = g_ohh; Al = g_ohl;
        Bh2 = g_wh + (size_t)3 * E_ * E_;
        Bl2 = g_wl + (size_t)3 * E_ * E_;
    }

    float acc[4][4][4];
#pragma unroll
    for (int a = 0; a < 4; a++)
#pragma unroll
        for (int b = 0; b < 4; b++)
#pragma unroll
            for (int c = 0; c < 4; c++) acc[a][b][c] = 0.f;

    auto load = [&](int c) {
        const uint32_t base = s0 + (c & 1) * GSTAGE;
        const int k0 = c * 32;
#pragma unroll
        for (int i = 0; i < 8; i++) {
            int g = i * 256 + tid;           // 0..2047
            int t = g >> 9;                  // 0..3 : Ah,Al,Bh,Bl
            int r = (g >> 2) & 127;
            int ch = g & 3;
            const __half* src = (t == 0) ? Ah : (t == 1) ? Al : (t == 2) ? Bh2 : Bl2;
            int row = ((t < 2) ? m0 : n0) + r;
            cp16(base + t * GT_BYTES + r * GROWB + ch * 16,
                 src + (size_t)row * E_ + k0 + ch * 8);
        }
    };

    load(0); CP_COMMIT();
    load(1); CP_COMMIT();

    const int rowoff = (lane & 7) + ((lane >> 3) & 1) * 8;
    for (int c = 0; c < 32; c++) {
        CP_WAIT1();
        __syncthreads();
        const uint32_t base = s0 + (c & 1) * GSTAGE;
#pragma unroll
        for (int ks = 0; ks < 2; ks++) {
            const int chunk = ks * 2 + (lane >> 4);
            uint32_t ah[4][4], al[4][4];
#pragma unroll
            for (int mi = 0; mi < 4; mi++) {
                uint32_t ra = base + (wm*64 + mi*16 + rowoff) * GROWB + chunk * 16;
                ldsm4(ra, ah[mi]);
                ldsm4(ra + GT_BYTES, al[mi]);
            }
#pragma unroll
            for (int p = 0; p < 2; p++) {
                uint32_t bh[4], bl[4];
                uint32_t rb = base + 2*GT_BYTES + (wn*32 + p*16 + rowoff) * GROWB + chunk * 16;
                ldsm4(rb, bh);
                ldsm4(rb + GT_BYTES, bl);
#pragma unroll
                for (int mi = 0; mi < 4; mi++) {
                    mma_fp16(acc[mi][2*p],   ah[mi], bh[0], bh[2]);
                    mma_fp16(acc[mi][2*p],   ah[mi], bl[0], bl[2]);
                    mma_fp16(acc[mi][2*p],   al[mi], bh[0], bh[2]);
                    mma_fp16(acc[mi][2*p+1], ah[mi], bh[1], bh[3]);
                    mma_fp16(acc[mi][2*p+1], ah[mi], bl[1], bl[3]);
                    mma_fp16(acc[mi][2*p+1], al[mi], bh[1], bh[3]);
                }
            }
        }
        __syncthreads();
        if (c + 2 < 32) load(c + 2);
        CP_COMMIT();
    }

    const int g = lane >> 2, tg2 = (lane & 3) * 2;
    if (MODE == 1) {
#pragma unroll
        for (int mi = 0; mi < 4; mi++) {
            int m = m0 + wm*64 + mi*16 + g;
#pragma unroll
            for (int ni = 0; ni < 4; ni++) {
                int n = n0 + wn*32 + ni*8 + tg2;
                float b0 = bc[n], b1 = bc[n+1];
                *(float2*)(out + (size_t)m * E_ + n) =
                    make_float2(acc[mi][ni][0] + b0, acc[mi][ni][1] + b1);
                *(float2*)(out + (size_t)(m+8) * E_ + n) =
                    make_float2(acc[mi][ni][2] + b0, acc[mi][ni][3] + b1);
            }
        }
        return;
    }

    // ---- MODE 0: transpose via smem, then per-row cumprod(cos) ----
    float* st = (float*)sm;   // [128][132] fp32
#pragma unroll
    for (int mi = 0; mi < 4; mi++) {
        int r = wm*64 + mi*16 + g;
#pragma unroll
        for (int ni = 0; ni < 4; ni++) {
            int n = wn*32 + ni*8 + tg2;
            st[(size_t)r * 132 + n]     = acc[mi][ni][0];
            st[(size_t)r * 132 + n + 1] = acc[mi][ni][1];
            st[(size_t)(r+8) * 132 + n]     = acc[mi][ni][2];
            st[(size_t)(r+8) * 132 + n + 1] = acc[mi][ni][3];
        }
    }
    __syncthreads();

    {
        const int head = tid >> 7;          // 0..1 (two heads per 128-col tile)
        const int r = tid & 127;
        const int m = m0 + r;
        const int b = m >> 11, sI = m & (S_ - 1);
        const int hglob = blockIdx.x * 2 + head;
        const int bh = b * H_ + hglob;
        const int z = blockIdx.z;
        const float* src = st + (size_t)r * 132 + head * 64;

        float run = 1.f;
        float val[64];
#pragma unroll
        for (int d = 0; d < 64; d++) { run *= __cosf(src[d]); val[d] = run; }

        if (z < 2) {
            const float sc = (z == 0) ? 0.125f : 1.0f;
            __half hb[64], lb[64];
#pragma unroll
            for (int d = 0; d < 64; d++) split16(val[d] * sc, hb[d], lb[d]);
            __half* dh = (z == 0 ? g_qh : g_kh) + ((size_t)bh * S_ + sI) * 64;
            __half* dl = (z == 0 ? g_ql : g_kl) + ((size_t)bh * S_ + sI) * 64;
#pragma unroll
            for (int j = 0; j < 8; j++) {
                ((uint4*)dh)[j] = ((uint4*)hb)[j];
                ((uint4*)dl)[j] = ((uint4*)lb)[j];
            }
        } else {
#pragma unroll
            for (int d = 0; d < 64; d++) {
                __half h, l; split16(val[d], h, l);
                g_vth[((size_t)bh * 64 + d) * S_ + sI] = h;
                g_vtl[((size_t)bh * 64 + d) * S_ + sI] = l;
            }
        }
    }
}

// ---------------- HMMA flash attention ---------------------------------------
// grid (S/128, BH), 256 threads. Q tile 128 rows, KV tiles 64, 2 stages.
// QK: hi/lo split (3 mma); P fp16 straight from C-frag; V hi/lo (2 mma).
#define FROWB 144
#define FQT  (128*FROWB)     // 18432
#define FKT  (64*FROWB)      // 9216
#define FSTAGE (4*FKT)       // 36864 : Kh, Kl, Vh, Vl
#define FSMEM (2*FQT + 2*FSTAGE)   // 110592

__global__ __launch_bounds__(256) void flash_kernel()
{
    extern __shared__ char sm[];
    const uint32_t s0 = smem_u32(sm);
    const uint32_t sQ = s0, sKV = s0 + 2 * FQT;
    const int tid = threadIdx.x, lane = tid & 31, warp = tid >> 5;
    const int bh = blockIdx.y;
    const int q0 = blockIdx.x * 128;

    const __half* Qh = g_qh + (size_t)bh * S_ * 64;
    const __half* Ql = g_ql + (size_t)bh * S_ * 64;
    const __half* Kh = g_kh + (size_t)bh * S_ * 64;
    const __half* Kl = g_kl + (size_t)bh * S_ * 64;
    const __half* Vh = g_vth + (size_t)bh * 64 * S_;
    const __half* Vl = g_vtl + (size_t)bh * 64 * S_;

    auto loadKV = [&](int t) {
        const uint32_t base = sKV + (t & 1) * FSTAGE;
        const int kv0 = t * 64;
#pragma unroll
        for (int i = 0; i < 8; i++) {
            int gi = i * 256 + tid;         // 0..2047
            int tl = gi >> 9;               // 0..3 : Kh,Kl,Vh,Vl
            int r = (gi >> 3) & 63;
            int ch = gi & 7;
            const __half* src;
            if (tl == 0)      src = Kh + (size_t)(kv0 + r) * 64 + ch * 8;
            else if (tl == 1) src = Kl + (size_t)(kv0 + r) * 64 + ch * 8;
            else if (tl == 2) src = Vh + (size_t)r * S_ + kv0 + ch * 8;
            else              src = Vl + (size_t)r * S_ + kv0 + ch * 8;
            cp16(base + tl * FKT + r * FROWB + ch * 16, src);
        }
    };

    // group 0: Q + stage 0; group 1: stage 1
    {
#pragma unroll
        for (int i = 0; i < 8; i++) {
            int gi = i * 256 + tid;
            int tl = gi >> 10;              // 0,1 : Qh, Ql
            int r = (gi >> 3) & 127;
            int ch = gi & 7;
            const __half* src = (tl ? Ql : Qh) + (size_t)(q0 + r) * 64 + ch * 8;
            cp16(sQ + tl * FQT + r * FROWB + ch * 16, src);
        }
        loadKV(0); CP_COMMIT();
        loadKV(1); CP_COMMIT();
    }

    float o[8][4];
#pragma unroll
    for (int i = 0; i < 8; i++)
#pragma unroll
        for (int j = 0; j < 4; j++) o[i][j] = 0.f;
    float m0r = -1e30f, m1r = -1e30f, l0r = 0.f, l1r = 0.f;

    uint32_t qhf[4][4], qlf[4][4];
    const int rowoff = (lane & 7) + ((lane >> 3) & 1) * 8;

    for (int t = 0; t < 32; t++) {
        CP_WAIT1();
        __syncthreads();
        if (t == 0) {
#pragma unroll
            for (int ks = 0; ks < 4; ks++) {
                uint32_t ra = sQ + (warp*16 + rowoff) * FROWB + (ks*2 + (lane>>4)) * 16;
                ldsm4(ra, qhf[ks]);
                ldsm4(ra + FQT, qlf[ks]);
            }
        }
        const uint32_t kb = sKV + (t & 1) * FSTAGE;

        float s[8][4];
#pragma unroll
        for (int i = 0; i < 8; i++)
#pragma unroll
            for (int j = 0; j < 4; j++) s[i][j] = 0.f;

#pragma unroll
        for (int ks = 0; ks < 4; ks++) {
            const int chunk = ks * 2 + (lane >> 4);
#pragma unroll
            for (int p = 0; p < 4; p++) {
                uint32_t kh[4], kl[4];
                uint32_t rb = kb + (p*16 + rowoff) * FROWB + chunk * 16;
                ldsm4(rb, kh);
                ldsm4(rb + FKT, kl);
                mma_fp16(s[2*p],   qhf[ks], kh[0], kh[2]);
                mma_fp16(s[2*p],   qhf[ks], kl[0], kl[2]);
                mma_fp16(s[2*p],   qlf[ks], kh[0], kh[2]);
                mma_fp16(s[2*p+1], qhf[ks], kh[1], kh[3]);
                mma_fp16(s[2*p+1], qhf[ks], kl[1], kl[3]);
                mma_fp16(s[2*p+1], qlf[ks], kh[1], kh[3]);
            }
        }

        // online softmax (rows: g = lane>>2 and g+8; quad-shuffles xor 1,2)
        float rm0 = -1e30f, rm1 = -1e30f;
#pragma unroll
        for (int ni = 0; ni < 8; ni++) {
            rm0 = fmaxf(rm0, fmaxf(s[ni][0], s[ni][1]));
            rm1 = fmaxf(rm1, fmaxf(s[ni][2], s[ni][3]));
        }
        rm0 = fmaxf(rm0, __shfl_xor_sync(0xffffffffu, rm0, 1));
        rm0 = fmaxf(rm0, __shfl_xor_sync(0xffffffffu, rm0, 2));
        rm1 = fmaxf(rm1, __shfl_xor_sync(0xffffffffu, rm1, 1));
        rm1 = fmaxf(rm1, __shfl_xor_sync(0xffffffffu, rm1, 2));
        float mn0 = fmaxf(m0r, rm0), mn1 = fmaxf(m1r, rm1);
        float sc0 = __expf(m0r - mn0), sc1 = __expf(m1r - mn1);

        uint32_t pf[8][2];
        float rs0 = 0.f, rs1 = 0.f;
#pragma unroll
        for (int ni = 0; ni < 8; ni++) {
            float p0 = __expf(s[ni][0] - mn0);
            float p1 = __expf(s[ni][1] - mn0);
            float p2 = __expf(s[ni][2] - mn1);
            float p3 = __expf(s[ni][3] - mn1);
            rs0 += p0 + p1; rs1 += p2 + p3;
            pf[ni][0] = pack2(p0, p1);
            pf[ni][1] = pack2(p2, p3);
        }
        rs0 += __shfl_xor_sync(0xffffffffu, rs0, 1);
        rs0 += __shfl_xor_sync(0xffffffffu, rs0, 2);
        rs1 += __shfl_xor_sync(0xffffffffu, rs1, 1);
        rs1 += __shfl_xor_sync(0xffffffffu, rs1, 2);
        l0r = l0r * sc0 + rs0;  m0r = mn0;
        l1r = l1r * sc1 + rs1;  m1r = mn1;
#pragma unroll
        for (int ni = 0; ni < 8; ni++) {
            o[ni][0] *= sc0; o[ni][1] *= sc0;
            o[ni][2] *= sc1; o[ni][3] *= sc1;
        }

        // O += P V   (A-frags come straight from P fragments)
        const uint32_t vb = kb + 2 * FKT;
#pragma unroll
        for (int ks = 0; ks < 4; ks++) {
            uint32_t a[4] = { pf[2*ks][0], pf[2*ks][1], pf[2*ks+1][0], pf[2*ks+1][1] };
            const int chunk = ks * 2 + (lane >> 4);
#pragma unroll
            for (int p = 0; p < 4; p++) {
                uint32_t vh[4], vl[4];
                uint32_t rb = vb + (p*16 + rowoff) * FROWB + chunk * 16;
                ldsm4(rb, vh);
                ldsm4(rb + FKT, vl);
                mma_fp16(o[2*p],   a, vh[0], vh[2]);
                mma_fp16(o[2*p],   a, vl[0], vl[2]);
                mma_fp16(o[2*p+1], a, vh[1], vh[3]);
                mma_fp16(o[2*p+1], a, vl[1], vl[3]);
            }
        }

        __syncthreads();
        if (t + 2 < 32) loadKV(t + 2);
        CP_COMMIT();
    }

    // epilogue: normalize, split hi/lo fp16, write [B,S,H,D] (= [M,E])
    const float inv0 = 1.f / l0r, inv1 = 1.f / l1r;
    const int g = lane >> 2, tg2 = (lane & 3) * 2;
    const int b = bh >> 4, h = bh & 15;
    const int sA = q0 + warp * 16 + g;
#pragma unroll
    for (int ni = 0; ni < 8; ni++) {
        int d = ni * 8 + tg2;
        size_t i0 = (((size_t)(b * S_ + sA)     * H_ + h) * D_ + d);
        size_t i1 = (((size_t)(b * S_ + sA + 8) * H_ + h) * D_ + d);
        __half h0,h1,h2,h3,l0,l1,l2,l3;
        split16(o[ni][0] * inv0, h0, l0);
        split16(o[ni][1] * inv0, h1, l1);
        split16(o[ni][2] * inv1, h2, l2);
        split16(o[ni][3] * inv1, h3, l3);
        *(__half2*)(g_ohh + i0) = __halves2half2(h0, h1);
        *(__half2*)(g_ohl + i0) = __halves2half2(l0, l1);
        *(__half2*)(g_ohh + i1) = __halves2half2(h2, h3);
        *(__half2*)(g_ohl + i1) = __halves2half2(l2, l3);
    }
}

// ---------------------------------------------------------------------------
extern "C" void kernel_launch(void* const* d_in, const int* in_sizes, int n_in,
                              void* d_out, int out_size)
{
    const float* x  = (const float*)d_in[0];
    const float* Wq = (const float*)d_in[1];
    const float* Wk = (const float*)d_in[2];
    const float* Wv = (const float*)d_in[3];
    const float* Wc = (const float*)d_in[4];
    const float* bc = (const float*)d_in[5];
    float* out = (float*)d_out;

    cudaFuncSetAttribute(gemm_kernel<0>, cudaFuncAttributeMaxDynamicSharedMemorySize, GSMEM);
    cudaFuncSetAttribute(gemm_kernel<1>, cudaFuncAttributeMaxDynamicSharedMemorySize, GSMEM);
    cudaFuncSetAttribute(flash_kernel,   cudaFuncAttributeMaxDynamicSharedMemorySize, FSMEM);

    // 1) fp32 -> fp16 hi/lo for x and all weights
    convert_kernel<<<dim3(4096, 5), 256>>>(x, Wq, Wk, Wv, Wc);

    // 2) QKV projections (HMMA split) + fused quantum cumprod(cos) epilogue
    gemm_kernel<0><<<dim3(E_/128, M_/128, 3), 256, GSMEM>>>(nullptr, nullptr);

    // 3) flash attention (HMMA split QK, fp16 P, split V)
    flash_kernel<<<dim3(S_/128, BH_), 256, FSMEM>>>();

    // 4) output projection (HMMA split) + bias
    gemm_kernel<1><<<dim3(E_/128, M_/128, 1), 256, GSMEM>>>(out, bc);
}